// round 2
// baseline (speedup 1.0000x reference)
#include <cuda_runtime.h>
#include <cstdint>

#define EPS   1e-5f
#define SLOPE 0.01f

// sizes (1,2,3,6); s^2 = (1,4,9,36); cumsum s^2 = (0,1,5,14) total 50; cumsum s = (0,1,3,6)
__constant__ int c_SZ[4] = {1, 2, 3, 6};
__constant__ int c_S2[4] = {1, 4, 9, 36};
__constant__ int c_PO[4] = {0, 1, 5, 14};
__constant__ int c_UB[4] = {0, 196608, 589824, 1179648}; // u bases = cumsum(s)*2*512*3*64

// scratch (static device globals; no allocation)
__device__ float g_pool[204800];   // 50 * 2 * 2048
__device__ float g_bo[51200];      // 50 * 2 * 512
__device__ float g_bhat[51200];
__device__ float g_q[460800];      // 50 * 2 * 512 * 9
__device__ float g_u[2359296];     // 12 * 2*512*3*64
__device__ float g_v[4194304];     // 2*512*64*64
__device__ float g_scale[512];
__device__ float g_shift[512];

// ---------------------------------------------------------------- K1: pools
__global__ void k_pool(const float* __restrict__ feats) {
    __shared__ float plane[4096];
    __shared__ float rowp[768];
    int nc = blockIdx.x; // n*2048+c
    const float* src = feats + (size_t)nc * 4096;
    for (int i = threadIdx.x; i < 4096; i += 256) plane[i] = src[i];
    __syncthreads();
    // row partials: per (branch, y, j) sum over x-window. layout base {0,64,192,384}
    for (int t = threadIdx.x; t < 768; t += 256) {
        int b, loc;
        if (t < 64)       { b = 0; loc = t; }
        else if (t < 192) { b = 1; loc = t - 64; }
        else if (t < 384) { b = 2; loc = t - 192; }
        else              { b = 3; loc = t - 384; }
        int s = c_SZ[b];
        int y = loc / s, j = loc - y * s;
        int xs = (j * 64) / s, xe = ((j + 1) * 64 + s - 1) / s;
        float a = 0.f;
        for (int x = xs; x < xe; x++) a += plane[y * 64 + x];
        rowp[t] = a;
    }
    __syncthreads();
    if (threadIdx.x < 50) {
        int t = threadIdx.x; int b, loc;
        if (t < 1)       { b = 0; loc = 0; }
        else if (t < 5)  { b = 1; loc = t - 1; }
        else if (t < 14) { b = 2; loc = t - 5; }
        else             { b = 3; loc = t - 14; }
        int s = c_SZ[b];
        int i = loc / s, j = loc - i * s;
        int ys = (i * 64) / s, ye = ((i + 1) * 64 + s - 1) / s;
        int xs = (j * 64) / s, xe = ((j + 1) * 64 + s - 1) / s;
        int rb = (b == 0) ? 0 : (b == 1) ? 64 : (b == 2) ? 192 : 384;
        float a = 0.f;
        for (int y = ys; y < ye; y++) a += rowp[rb + y * s + j];
        g_pool[c_PO[b] * 4096 + nc * c_S2[b] + loc] = a / (float)((ye - ys) * (xe - xs));
    }
}

// ------------------------------------------------- K2: 1x1 convs (per-branch)
__global__ void k_conv1(const float* __restrict__ w0, const float* __restrict__ w1,
                        const float* __restrict__ w2, const float* __restrict__ w3) {
    __shared__ float pcol[2048];
    int bx = blockIdx.x; // 100 = sum 2*s^2
    int b, loc;
    if (bx < 2)       { b = 0; loc = bx; }
    else if (bx < 10) { b = 1; loc = bx - 2; }
    else if (bx < 28) { b = 2; loc = bx - 10; }
    else              { b = 3; loc = bx - 28; }
    int s2 = c_S2[b];
    int n = loc / s2, ij = loc - n * s2;
    const float* W = (b == 0) ? w0 : (b == 1) ? w1 : (b == 2) ? w2 : w3;
    int pb = c_PO[b] * 4096 + n * 2048 * s2 + ij;
    for (int c = threadIdx.x; c < 2048; c += 512) pcol[c] = g_pool[pb + c * s2];
    __syncthreads();
    int warp = threadIdx.x >> 5, lane = threadIdx.x & 31;
    for (int o = warp; o < 512; o += 16) {
        const float* wr = W + (size_t)o * 2048;
        float acc = 0.f;
        for (int c = lane * 4; c < 2048; c += 128) {
            float4 wv = *reinterpret_cast<const float4*>(wr + c);
            acc += wv.x * pcol[c] + wv.y * pcol[c + 1] + wv.z * pcol[c + 2] + wv.w * pcol[c + 3];
        }
        #pragma unroll
        for (int off = 16; off; off >>= 1) acc += __shfl_xor_sync(0xffffffffu, acc, off);
        if (lane == 0) g_bo[c_PO[b] * 1024 + (n * 512 + o) * s2 + ij] = acc;
    }
}

// ---------------------------------------- K3: per-branch BN (batch stats) + lrelu
__global__ void k_bnbr(const float* __restrict__ g0, const float* __restrict__ b0,
                       const float* __restrict__ g1, const float* __restrict__ b1,
                       const float* __restrict__ g2, const float* __restrict__ b2,
                       const float* __restrict__ g3, const float* __restrict__ b3) {
    int b = blockIdx.x >> 9, o = blockIdx.x & 511;
    int s2 = c_S2[b], cnt = 2 * s2;
    int tid = threadIdx.x;
    __shared__ float rs[128], rq[128];
    float v = 0.f; int idx = 0;
    if (tid < cnt) {
        int n = tid / s2, ij = tid - n * s2;
        idx = c_PO[b] * 1024 + (n * 512 + o) * s2 + ij;
        v = g_bo[idx];
    }
    rs[tid] = (tid < cnt) ? v : 0.f;
    rq[tid] = (tid < cnt) ? v * v : 0.f;
    __syncthreads();
    for (int st = 64; st > 0; st >>= 1) {
        if (tid < st) { rs[tid] += rs[tid + st]; rq[tid] += rq[tid + st]; }
        __syncthreads();
    }
    float mean = rs[0] / cnt, var = rq[0] / cnt - mean * mean;
    const float* gp = (b == 0) ? g0 : (b == 1) ? g1 : (b == 2) ? g2 : g3;
    const float* bp = (b == 0) ? b0 : (b == 1) ? b1 : (b == 2) ? b2 : b3;
    float sc = gp[o] * rsqrtf(var + EPS);
    float sh = bp[o] - mean * sc;
    if (tid < cnt) {
        float y = v * sc + sh;
        g_bhat[idx] = (y >= 0.f) ? y : SLOPE * y;
    }
}

// ---------------- K4: q[b][n][o][tap][ij] = sum_c wb[o, 512*b+c, tap]*bhat
// (concat order: branches occupy channels 0..2047; feats occupy 2048..4095)
__global__ void k_qgemm(const float* __restrict__ wb) {
    int tap = blockIdx.x, ot = blockIdx.y, b = blockIdx.z;
    int s2 = c_S2[b];
    __shared__ float sm[64][72];
    int ol = threadIdx.x & 63, n = threadIdx.x >> 6;
    int o = ot * 64 + ol;
    float acc[36];
    #pragma unroll
    for (int e = 0; e < 36; e++) acc[e] = 0.f;
    int basec = 512 * b;
    for (int cc = 0; cc < 512; cc += 64) {
        __syncthreads();
        int tot = 64 * 2 * s2;
        for (int t = threadIdx.x; t < tot; t += 128) {
            int c = t / (2 * s2), r = t - c * (2 * s2);
            int nn = r / s2, ij = r - nn * s2;
            sm[c][r] = g_bhat[c_PO[b] * 1024 + (nn * 512 + cc + c) * s2 + ij];
        }
        __syncthreads();
        for (int c = 0; c < 64; c++) {
            float wv = wb[(size_t)(o * 4096 + basec + cc + c) * 9 + tap];
            const float* row = &sm[c][n * s2];
            #pragma unroll
            for (int e = 0; e < 36; e++)
                if (e < s2) acc[e] += wv * row[e];
        }
    }
    int qb = c_PO[b] * 9216;
    for (int e = 0; e < s2; e++)
        g_q[qb + ((n * 512 + o) * 9 + tap) * s2 + e] = acc[e];
}

// ------------- K5a: H-direction upsample of q, folding ky taps (zero padded)
__global__ void k_upsH() {
    int idx = blockIdx.x * 256 + threadIdx.x;
    if (idx >= 2359296) return;
    int b, loc;
    if (idx < 196608)       { b = 0; loc = idx; }
    else if (idx < 589824)  { b = 1; loc = idx - 196608; }
    else if (idx < 1179648) { b = 2; loc = idx - 589824; }
    else                    { b = 3; loc = idx - 1179648; }
    int s = c_SZ[b], s2 = c_S2[b];
    int j = loc % s; int t = loc / s;
    int y = t & 63; t >>= 6;
    int kx = t % 3; t /= 3;
    int o = t & 511; int n = t >> 9;
    int qb = c_PO[b] * 9216;
    float fs = (s > 1) ? (float)(s - 1) / 63.0f : 0.0f;
    float acc = 0.f;
    #pragma unroll
    for (int ky = 0; ky < 3; ky++) {
        int Y = y + ky - 1;
        if (Y < 0 || Y > 63) continue;
        float pos = Y * fs;
        int i0 = (int)pos; float w = pos - i0; int i1 = min(i0 + 1, s - 1);
        const float* qq = &g_q[qb + ((n * 512 + o) * 9 + ky * 3 + kx) * s2 + j];
        acc += (1.f - w) * qq[i0 * s] + w * qq[i1 * s];
    }
    g_u[c_UB[b] + loc] = acc;
}

// ------------- K5b: W-direction upsample, folding kx taps + branch sum -> v
__global__ void k_upsW() {
    int idx = blockIdx.x * 256 + threadIdx.x;
    if (idx >= 4194304) return;
    int x = idx & 63, y = (idx >> 6) & 63;
    int no = idx >> 12; // n*512+o
    float acc = 0.f;
    #pragma unroll
    for (int b = 0; b < 4; b++) {
        int s = c_SZ[b];
        float fs = (s > 1) ? (float)(s - 1) / 63.f : 0.f;
        #pragma unroll
        for (int kx = 0; kx < 3; kx++) {
            int X = x + kx - 1;
            if (X < 0 || X > 63) continue;
            float pos = X * fs;
            int j0 = (int)pos; float w = pos - j0; int j1 = min(j0 + 1, s - 1);
            const float* uu = &g_u[c_UB[b] + ((no * 3 + kx) * 64 + y) * s];
            acc += (1.f - w) * uu[j0] + w * uu[j1];
        }
    }
    g_v[idx] = acc;
}

// ------------------------------- K6: conv3x3 on feats (2048 ch) via TF32 mma
// feats occupy wb channels 2048..4095.
__device__ __forceinline__ float tf32r(float x) {
    uint32_t u;
    asm("cvt.rna.tf32.f32 %0, %1;" : "=r"(u) : "f"(x));
    return __uint_as_float(u);
}
__device__ __forceinline__ void mma8(float* c, uint32_t a0, uint32_t a1, uint32_t a2, uint32_t a3,
                                     uint32_t b0, uint32_t b1) {
    asm volatile("mma.sync.aligned.m16n8k8.row.col.f32.tf32.tf32.f32 "
                 "{%0,%1,%2,%3}, {%4,%5,%6,%7}, {%8,%9}, {%0,%1,%2,%3};\n"
                 : "+f"(c[0]), "+f"(c[1]), "+f"(c[2]), "+f"(c[3])
                 : "r"(a0), "r"(a1), "r"(a2), "r"(a3), "r"(b0), "r"(b1));
}

__global__ __launch_bounds__(512, 1) void k_conv3(const float* __restrict__ feats,
                                                  const float* __restrict__ wb,
                                                  float* __restrict__ out) {
    __shared__ float As[9216];   // [o_local(128)][72]  (72 = 8ci * 9tap, matches global order)
    __shared__ float Ps[2592];   // [ci(8)][18][18] patch with halo
    int o0 = blockIdx.x * 128;
    int by = blockIdx.y;          // 0..31
    int n = by >> 4;
    int t = by & 15;
    int ty0 = (t >> 2) * 16, tx0 = (t & 3) * 16;
    int tid = threadIdx.x;
    int warp = tid >> 5, lane = tid & 31;
    int wm = warp >> 3, wn = warp & 7;       // 2 x 8 warp grid -> warp tile 64 x 32px
    int gid = lane >> 2, tig = lane & 3;

    float acc[4][4][4];
    #pragma unroll
    for (int mi = 0; mi < 4; mi++)
        #pragma unroll
        for (int ni = 0; ni < 4; ni++)
            #pragma unroll
            for (int r = 0; r < 4; r++) acc[mi][ni][r] = 0.f;

    int py[4], px[4];
    #pragma unroll
    for (int ni = 0; ni < 4; ni++) {
        int p = wn * 32 + ni * 8 + gid;
        py[ni] = p >> 4; px[ni] = p & 15;
    }

    // feats start at wb channel 2048 -> byte offset per o: (2048*9) within the 4096*9 row
    const float* wbase = wb + (size_t)o0 * 36864 + 18432;   // o0*4096*9 + 2048*9

    for (int cc = 0; cc < 2048; cc += 8) {
        __syncthreads();
        // stage weights: 128 o x 72 (8ci*9tap) contiguous per o
        for (int i4 = tid; i4 < 2304; i4 += 512) {
            int i = i4 * 4;
            int ol = i / 72;
            int r = i - ol * 72;
            float4 wv = *reinterpret_cast<const float4*>(wbase + (size_t)ol * 36864 + cc * 9 + r);
            float4 sv;
            sv.x = tf32r(wv.x); sv.y = tf32r(wv.y); sv.z = tf32r(wv.z); sv.w = tf32r(wv.w);
            *reinterpret_cast<float4*>(&As[i]) = sv;
        }
        // stage input patch 8ch x 18x18 (zero pad)
        for (int i = tid; i < 2592; i += 512) {
            int ci = i / 324;
            int rr = i - ci * 324;
            int r = rr / 18, cx = rr - r * 18;
            int gy = ty0 + r - 1, gx = tx0 + cx - 1;
            float v = 0.f;
            if ((unsigned)gy < 64u && (unsigned)gx < 64u)
                v = feats[(((size_t)(n * 2048 + cc + ci)) * 64 + gy) * 64 + gx];
            Ps[i] = tf32r(v);
        }
        __syncthreads();
        #pragma unroll
        for (int ky = 0; ky < 3; ky++) {
            #pragma unroll
            for (int kx = 0; kx < 3; kx++) {
                int tap = ky * 3 + kx;
                uint32_t bf[4][2];
                #pragma unroll
                for (int ni = 0; ni < 4; ni++) {
                    int off = (py[ni] + ky) * 18 + px[ni] + kx;
                    bf[ni][0] = __float_as_uint(Ps[tig * 324 + off]);
                    bf[ni][1] = __float_as_uint(Ps[(tig + 4) * 324 + off]);
                }
                #pragma unroll
                for (int mi = 0; mi < 4; mi++) {
                    int m = wm * 64 + mi * 16 + gid;
                    uint32_t a0 = __float_as_uint(As[m * 72 + tig * 9 + tap]);
                    uint32_t a1 = __float_as_uint(As[(m + 8) * 72 + tig * 9 + tap]);
                    uint32_t a2 = __float_as_uint(As[m * 72 + (tig + 4) * 9 + tap]);
                    uint32_t a3 = __float_as_uint(As[(m + 8) * 72 + (tig + 4) * 9 + tap]);
                    #pragma unroll
                    for (int ni = 0; ni < 4; ni++)
                        mma8(acc[mi][ni], a0, a1, a2, a3, bf[ni][0], bf[ni][1]);
                }
            }
        }
    }
    // epilogue: z = conv(feats) + branch contribution v; store pre-BN z to out
    #pragma unroll
    for (int mi = 0; mi < 4; mi++) {
        int oa = o0 + wm * 64 + mi * 16 + gid;
        #pragma unroll
        for (int ni = 0; ni < 4; ni++) {
            int pA = wn * 32 + ni * 8 + 2 * tig;
            #pragma unroll
            for (int r = 0; r < 4; r++) {
                int o = oa + ((r >= 2) ? 8 : 0);
                int p = pA + (r & 1);
                int yy = ty0 + (p >> 4), xx = tx0 + (p & 15);
                size_t gi = (((size_t)(n * 512 + o)) * 64 + yy) * 64 + xx;
                out[gi] = acc[mi][ni][r] + g_v[gi];
            }
        }
    }
}

// ----------------------------------------------- K7: final BN batch stats
__global__ void k_stats(const float* __restrict__ z, const float* __restrict__ gb,
                        const float* __restrict__ bbp) {
    int o = blockIdx.x;
    int tid = threadIdx.x;
    float s = 0.f, sq = 0.f;
    for (int n = 0; n < 2; n++) {
        const float* p = z + ((size_t)(n * 512 + o)) * 4096;
        for (int i = tid; i < 4096; i += 256) { float v = p[i]; s += v; sq += v * v; }
    }
    __shared__ float rs[256], rq[256];
    rs[tid] = s; rq[tid] = sq; __syncthreads();
    for (int st = 128; st > 0; st >>= 1) {
        if (tid < st) { rs[tid] += rs[tid + st]; rq[tid] += rq[tid + st]; }
        __syncthreads();
    }
    if (tid == 0) {
        float mean = rs[0] * (1.f / 8192.f);
        float var = rq[0] * (1.f / 8192.f) - mean * mean;
        float sc = gb[o] * rsqrtf(var + EPS);
        g_scale[o] = sc;
        g_shift[o] = bbp[o] - mean * sc;
    }
}

// ----------------------------------------------- K8: apply BN + lrelu in place
__global__ void k_apply(float* __restrict__ out) {
    int idx = blockIdx.x * 256 + threadIdx.x;
    if (idx >= 4194304) return;
    int o = (idx >> 12) & 511;
    float v = out[idx] * g_scale[o] + g_shift[o];
    out[idx] = (v >= 0.f) ? v : SLOPE * v;
}

extern "C" void kernel_launch(void* const* d_in, const int* in_sizes, int n_in,
                              void* d_out, int out_size) {
    const float* feats = (const float*)d_in[0];
    const float* w0 = (const float*)d_in[1];
    const float* g0 = (const float*)d_in[2];
    const float* b0 = (const float*)d_in[3];
    const float* w1 = (const float*)d_in[4];
    const float* g1 = (const float*)d_in[5];
    const float* b1 = (const float*)d_in[6];
    const float* w2 = (const float*)d_in[7];
    const float* g2 = (const float*)d_in[8];
    const float* b2 = (const float*)d_in[9];
    const float* w3 = (const float*)d_in[10];
    const float* g3 = (const float*)d_in[11];
    const float* b3 = (const float*)d_in[12];
    const float* wb = (const float*)d_in[13];
    const float* gb = (const float*)d_in[14];
    const float* bb = (const float*)d_in[15];
    float* out = (float*)d_out;

    k_pool<<<4096, 256>>>(feats);
    k_conv1<<<100, 512>>>(w0, w1, w2, w3);
    k_bnbr<<<2048, 128>>>(g0, b0, g1, b1, g2, b2, g3, b3);
    k_qgemm<<<dim3(9, 8, 4), 128>>>(wb);
    k_upsH<<<(2359296 + 255) / 256, 256>>>();
    k_upsW<<<(4194304 + 255) / 256, 256>>>();
    k_conv3<<<dim3(4, 32), 512>>>(feats, wb, out);
    k_stats<<<512, 256>>>(out, gb, bb);
    k_apply<<<(4194304 + 255) / 256, 256>>>(out);
}

// round 4
// speedup vs baseline: 1.5861x; 1.5861x over previous
#include <cuda_runtime.h>
#include <cstdint>

#define EPS   1e-5f
#define SLOPE 0.01f

__constant__ int c_SZ[4] = {1, 2, 3, 6};
__constant__ int c_S2[4] = {1, 4, 9, 36};
__constant__ int c_PO[4] = {0, 1, 5, 14};
__constant__ int c_UB[4] = {0, 196608, 589824, 1179648};

// scratch (static device globals; no allocation)
__device__ float g_pool[204800];
__device__ float g_bo[51200];
__device__ float g_bhat[51200];
__device__ float g_q[460800];
__device__ float g_u[2359296];
__device__ float g_v[4194304];
__device__ float g_scale[512];
__device__ float g_shift[512];
// pre-converted TF32 operands for the big conv
__device__ float g_wA[9961472];    // [4 otile][256 chunk][128 o][76 pad]  = 39.8MB
__device__ float g_fB[21495808];   // [32 (n,blk)][2048 c][328 pad patch] = 86MB

// ---------------------------------------------------------------- helpers
__device__ __forceinline__ float tf32r(float x) {
    uint32_t u;
    asm("cvt.rna.tf32.f32 %0, %1;" : "=r"(u) : "f"(x));
    return __uint_as_float(u);
}
__device__ __forceinline__ uint32_t smem_u32(const void* p) {
    uint32_t a;
    asm("{ .reg .u64 t; cvta.to.shared.u64 t, %1; cvt.u32.u64 %0, t; }" : "=r"(a) : "l"(p));
    return a;
}
__device__ __forceinline__ void cp16(uint32_t dst, const void* src) {
    asm volatile("cp.async.cg.shared.global [%0], [%1], 16;" :: "r"(dst), "l"(src));
}
__device__ __forceinline__ void cp_commit() {
    asm volatile("cp.async.commit_group;" ::: "memory");
}
template <int N> __device__ __forceinline__ void cp_wait() {
    asm volatile("cp.async.wait_group %0;" :: "n"(N) : "memory");
}
__device__ __forceinline__ void mma8(float* c, uint32_t a0, uint32_t a1, uint32_t a2, uint32_t a3,
                                     uint32_t b0, uint32_t b1) {
    asm volatile("mma.sync.aligned.m16n8k8.row.col.f32.tf32.tf32.f32 "
                 "{%0,%1,%2,%3}, {%4,%5,%6,%7}, {%8,%9}, {%0,%1,%2,%3};\n"
                 : "+f"(c[0]), "+f"(c[1]), "+f"(c[2]), "+f"(c[3])
                 : "r"(a0), "r"(a1), "r"(a2), "r"(a3), "r"(b0), "r"(b1));
}

// ---------------------------------------------------------------- K1: pools
__global__ void k_pool(const float* __restrict__ feats) {
    __shared__ float plane[4096];
    __shared__ float rowp[768];
    int nc = blockIdx.x;
    const float* src = feats + (size_t)nc * 4096;
    for (int i = threadIdx.x; i < 4096; i += 256) plane[i] = src[i];
    __syncthreads();
    for (int t = threadIdx.x; t < 768; t += 256) {
        int b, loc;
        if (t < 64)       { b = 0; loc = t; }
        else if (t < 192) { b = 1; loc = t - 64; }
        else if (t < 384) { b = 2; loc = t - 192; }
        else              { b = 3; loc = t - 384; }
        int s = c_SZ[b];
        int y = loc / s, j = loc - y * s;
        int xs = (j * 64) / s, xe = ((j + 1) * 64 + s - 1) / s;
        float a = 0.f;
        for (int x = xs; x < xe; x++) a += plane[y * 64 + x];
        rowp[t] = a;
    }
    __syncthreads();
    if (threadIdx.x < 50) {
        int t = threadIdx.x; int b, loc;
        if (t < 1)       { b = 0; loc = 0; }
        else if (t < 5)  { b = 1; loc = t - 1; }
        else if (t < 14) { b = 2; loc = t - 5; }
        else             { b = 3; loc = t - 14; }
        int s = c_SZ[b];
        int i = loc / s, j = loc - i * s;
        int ys = (i * 64) / s, ye = ((i + 1) * 64 + s - 1) / s;
        int xs = (j * 64) / s, xe = ((j + 1) * 64 + s - 1) / s;
        int rb = (b == 0) ? 0 : (b == 1) ? 64 : (b == 2) ? 192 : 384;
        float a = 0.f;
        for (int y = ys; y < ye; y++) a += rowp[rb + y * s + j];
        g_pool[c_PO[b] * 4096 + nc * c_S2[b] + loc] = a / (float)((ye - ys) * (xe - xs));
    }
}

// ------------------------------------------------- K2: 1x1 convs
__global__ void k_conv1(const float* __restrict__ w0, const float* __restrict__ w1,
                        const float* __restrict__ w2, const float* __restrict__ w3) {
    __shared__ float pcol[2048];
    int bx = blockIdx.x;
    int b, loc;
    if (bx < 2)       { b = 0; loc = bx; }
    else if (bx < 10) { b = 1; loc = bx - 2; }
    else if (bx < 28) { b = 2; loc = bx - 10; }
    else              { b = 3; loc = bx - 28; }
    int s2 = c_S2[b];
    int n = loc / s2, ij = loc - n * s2;
    const float* W = (b == 0) ? w0 : (b == 1) ? w1 : (b == 2) ? w2 : w3;
    int pb = c_PO[b] * 4096 + n * 2048 * s2 + ij;
    for (int c = threadIdx.x; c < 2048; c += 512) pcol[c] = g_pool[pb + c * s2];
    __syncthreads();
    int warp = threadIdx.x >> 5, lane = threadIdx.x & 31;
    for (int o = warp; o < 512; o += 16) {
        const float* wr = W + (size_t)o * 2048;
        float acc = 0.f;
        for (int c = lane * 4; c < 2048; c += 128) {
            float4 wv = *reinterpret_cast<const float4*>(wr + c);
            acc += wv.x * pcol[c] + wv.y * pcol[c + 1] + wv.z * pcol[c + 2] + wv.w * pcol[c + 3];
        }
        #pragma unroll
        for (int off = 16; off; off >>= 1) acc += __shfl_xor_sync(0xffffffffu, acc, off);
        if (lane == 0) g_bo[c_PO[b] * 1024 + (n * 512 + o) * s2 + ij] = acc;
    }
}

// ---------------------------------------- K3: per-branch BN + lrelu
__global__ void k_bnbr(const float* __restrict__ g0, const float* __restrict__ b0,
                       const float* __restrict__ g1, const float* __restrict__ b1,
                       const float* __restrict__ g2, const float* __restrict__ b2,
                       const float* __restrict__ g3, const float* __restrict__ b3) {
    int b = blockIdx.x >> 9, o = blockIdx.x & 511;
    int s2 = c_S2[b], cnt = 2 * s2;
    int tid = threadIdx.x;
    __shared__ float rs[128], rq[128];
    float v = 0.f; int idx = 0;
    if (tid < cnt) {
        int n = tid / s2, ij = tid - n * s2;
        idx = c_PO[b] * 1024 + (n * 512 + o) * s2 + ij;
        v = g_bo[idx];
    }
    rs[tid] = (tid < cnt) ? v : 0.f;
    rq[tid] = (tid < cnt) ? v * v : 0.f;
    __syncthreads();
    for (int st = 64; st > 0; st >>= 1) {
        if (tid < st) { rs[tid] += rs[tid + st]; rq[tid] += rq[tid + st]; }
        __syncthreads();
    }
    float mean = rs[0] / cnt, var = rq[0] / cnt - mean * mean;
    const float* gp = (b == 0) ? g0 : (b == 1) ? g1 : (b == 2) ? g2 : g3;
    const float* bp = (b == 0) ? b0 : (b == 1) ? b1 : (b == 2) ? b2 : b3;
    float sc = gp[o] * rsqrtf(var + EPS);
    float sh = bp[o] - mean * sc;
    if (tid < cnt) {
        float y = v * sc + sh;
        g_bhat[idx] = (y >= 0.f) ? y : SLOPE * y;
    }
}

// ---------------- K4: q-GEMM (branch channels 0..2047 of wb)
__global__ void k_qgemm(const float* __restrict__ wb) {
    int tap = blockIdx.x, ot = blockIdx.y, b = blockIdx.z;
    int s2 = c_S2[b];
    __shared__ float sm[64][72];
    int ol = threadIdx.x & 63, n = threadIdx.x >> 6;
    int o = ot * 64 + ol;
    float acc[36];
    #pragma unroll
    for (int e = 0; e < 36; e++) acc[e] = 0.f;
    int basec = 512 * b;
    for (int cc = 0; cc < 512; cc += 64) {
        __syncthreads();
        int tot = 64 * 2 * s2;
        for (int t = threadIdx.x; t < tot; t += 128) {
            int c = t / (2 * s2), r = t - c * (2 * s2);
            int nn = r / s2, ij = r - nn * s2;
            sm[c][r] = g_bhat[c_PO[b] * 1024 + (nn * 512 + cc + c) * s2 + ij];
        }
        __syncthreads();
        for (int c = 0; c < 64; c++) {
            float wv = wb[(size_t)(o * 4096 + basec + cc + c) * 9 + tap];
            const float* row = &sm[c][n * s2];
            #pragma unroll
            for (int e = 0; e < 36; e++)
                if (e < s2) acc[e] += wv * row[e];
        }
    }
    int qb = c_PO[b] * 9216;
    for (int e = 0; e < s2; e++)
        g_q[qb + ((n * 512 + o) * 9 + tap) * s2 + e] = acc[e];
}

// ------------- K5a: H upsample
__global__ void k_upsH() {
    int idx = blockIdx.x * 256 + threadIdx.x;
    if (idx >= 2359296) return;
    int b, loc;
    if (idx < 196608)       { b = 0; loc = idx; }
    else if (idx < 589824)  { b = 1; loc = idx - 196608; }
    else if (idx < 1179648) { b = 2; loc = idx - 589824; }
    else                    { b = 3; loc = idx - 1179648; }
    int s = c_SZ[b], s2 = c_S2[b];
    int j = loc % s; int t = loc / s;
    int y = t & 63; t >>= 6;
    int kx = t % 3; t /= 3;
    int o = t & 511; int n = t >> 9;
    int qb = c_PO[b] * 9216;
    float fs = (s > 1) ? (float)(s - 1) / 63.0f : 0.0f;
    float acc = 0.f;
    #pragma unroll
    for (int ky = 0; ky < 3; ky++) {
        int Y = y + ky - 1;
        if (Y < 0 || Y > 63) continue;
        float pos = Y * fs;
        int i0 = (int)pos; float w = pos - i0; int i1 = min(i0 + 1, s - 1);
        const float* qq = &g_q[qb + ((n * 512 + o) * 9 + ky * 3 + kx) * s2 + j];
        acc += (1.f - w) * qq[i0 * s] + w * qq[i1 * s];
    }
    g_u[c_UB[b] + loc] = acc;
}

// ------------- K5b: W upsample + branch sum -> v
__global__ void k_upsW() {
    int idx = blockIdx.x * 256 + threadIdx.x;
    if (idx >= 4194304) return;
    int x = idx & 63, y = (idx >> 6) & 63;
    int no = idx >> 12;
    float acc = 0.f;
    #pragma unroll
    for (int b = 0; b < 4; b++) {
        int s = c_SZ[b];
        float fs = (s > 1) ? (float)(s - 1) / 63.f : 0.f;
        #pragma unroll
        for (int kx = 0; kx < 3; kx++) {
            int X = x + kx - 1;
            if (X < 0 || X > 63) continue;
            float pos = X * fs;
            int j0 = (int)pos; float w = pos - j0; int j1 = min(j0 + 1, s - 1);
            const float* uu = &g_u[c_UB[b] + ((no * 3 + kx) * 64 + y) * s];
            acc += (1.f - w) * uu[j0] + w * uu[j1];
        }
    }
    g_v[idx] = acc;
}

// ----------------- prep: weights -> tf32, padded [otile][chunk][o(128)][76]
__global__ void k_prepW(const float* __restrict__ wb) {
    int bx = blockIdx.x;          // 0..1023 = ot*256 + j
    int ot = bx >> 8, j = bx & 255;
    size_t dbase = (size_t)bx * 9728;
    for (int w = threadIdx.x; w < 9728; w += 512) {
        int ow = w / 76, r = w - ow * 76;
        float v = 0.f;
        if (r < 72)
            v = tf32r(wb[(size_t)(ot * 128 + ow) * 36864 + 18432 + j * 72 + r]);
        g_wA[dbase + w] = v;
    }
}

// ----------------- prep: image patches -> tf32, [nb(32)][c(2048)][328]
// nb = n*16 + blk; blk -> 16x16 tile at (ty0,tx0); 18x18 halo with zero pad.
__global__ void k_prepP(const float* __restrict__ feats) {
    int c = blockIdx.x;           // 0..2047
    int nb = blockIdx.y;          // 0..31
    int n = nb >> 4, t = nb & 15;
    int ty0 = (t >> 2) * 16, tx0 = (t & 3) * 16;
    int tid = threadIdx.x;        // 0..327
    float v = 0.f;
    if (tid < 324) {
        int r = tid / 18, x = tid - r * 18;
        int gy = ty0 + r - 1, gx = tx0 + x - 1;
        if ((unsigned)gy < 64u && (unsigned)gx < 64u)
            v = tf32r(feats[(((size_t)(n * 2048 + c)) << 12) + (gy << 6) + gx]);
    }
    g_fB[((size_t)nb * 2048 + c) * 328 + tid] = v;
}

// ======================= K6: conv3x3 via legacy TF32 mma.sync ==============
// CTA: 128 o x 256 px (16x16). 16 warps: wm(2) x wn(8), warp tile 64o x 32px.
// K chunk = 8 channels x 9 taps. cp.async 3-stage pipeline, conflict-free smem.
#define ASTRIDE 76
#define PSTRIDE 328
#define ABYTES  38912        // 128*76*4
#define PBYTES  10496        // 8*328*4
#define STAGEB  49408
#define NCP     3088         // (ABYTES+PBYTES)/16
#define NCPA    2432         // ABYTES/16
#define CONV_SMEM (3 * STAGEB)   // 148224

__global__ __launch_bounds__(512, 1) void k_conv3_lg(float* __restrict__ out) {
    extern __shared__ char smem[];
    uint32_t sb = smem_u32(smem);
    int tid = threadIdx.x;
    int warp = tid >> 5, lane = tid & 31;
    int bx = blockIdx.x;          // o-tile 0..3
    int nb = blockIdx.y;          // 0..31 = n*16 + blk
    int o0 = bx * 128;
    int n2 = nb >> 4;
    int t = nb & 15;
    int ty0 = (t >> 2) * 16, tx0 = (t & 3) * 16;
    int wm = warp >> 3, wn = warp & 7;
    int gid = lane >> 2, tig = lane & 3;

    float acc[4][4][4];
    #pragma unroll
    for (int mi = 0; mi < 4; mi++)
        #pragma unroll
        for (int ni = 0; ni < 4; ni++)
            #pragma unroll
            for (int r = 0; r < 4; r++) acc[mi][ni][r] = 0.f;

    int py[4], px[4];
    #pragma unroll
    for (int ni = 0; ni < 4; ni++) {
        int p = wn * 32 + ni * 8 + gid;
        py[ni] = p >> 4; px[ni] = p & 15;
    }

    const char* srcAbase = (const char*)(g_wA + (size_t)bx * 256 * 9728);
    const char* srcPbase = (const char*)(g_fB + (size_t)nb * 2048 * 328);

    // stage chunk j into buffer j%3
    auto stage = [&](int j) {
        uint32_t dA = sb + (j % 3) * STAGEB;
        uint32_t dP = dA + ABYTES;
        const char* sA = srcAbase + (size_t)j * ABYTES;
        const char* sP = srcPbase + (size_t)j * PBYTES;
        for (int i = tid; i < NCP; i += 512) {
            if (i < NCPA) cp16(dA + i * 16, sA + i * 16);
            else          cp16(dP + (i - NCPA) * 16, sP + (size_t)(i - NCPA) * 16);
        }
        cp_commit();
    };

    stage(0);
    stage(1);

    for (int j = 0; j < 256; j++) {
        if (j < 255) cp_wait<1>(); else cp_wait<0>();
        __syncthreads();
        if (j + 2 < 256) stage(j + 2);

        const float* As = (const float*)(smem + (j % 3) * STAGEB);
        const float* Ps = As + 128 * ASTRIDE;

        #pragma unroll
        for (int ky = 0; ky < 3; ky++) {
            #pragma unroll
            for (int kx = 0; kx < 3; kx++) {
                int tap = ky * 3 + kx;
                uint32_t bf[4][2];
                #pragma unroll
                for (int ni = 0; ni < 4; ni++) {
                    int off = (py[ni] + ky) * 18 + px[ni] + kx;
                    bf[ni][0] = __float_as_uint(Ps[tig * PSTRIDE + off]);
                    bf[ni][1] = __float_as_uint(Ps[(tig + 4) * PSTRIDE + off]);
                }
                #pragma unroll
                for (int mi = 0; mi < 4; mi++) {
                    int m = wm * 64 + mi * 16 + gid;
                    uint32_t a0 = __float_as_uint(As[m * ASTRIDE + tig * 9 + tap]);
                    uint32_t a1 = __float_as_uint(As[(m + 8) * ASTRIDE + tig * 9 + tap]);
                    uint32_t a2 = __float_as_uint(As[m * ASTRIDE + (tig + 4) * 9 + tap]);
                    uint32_t a3 = __float_as_uint(As[(m + 8) * ASTRIDE + (tig + 4) * 9 + tap]);
                    #pragma unroll
                    for (int ni = 0; ni < 4; ni++)
                        mma8(acc[mi][ni], a0, a1, a2, a3, bf[ni][0], bf[ni][1]);
                }
            }
        }
        __syncthreads();
    }

    // epilogue: z = conv(feats) + branch contribution v; store pre-BN z
    #pragma unroll
    for (int mi = 0; mi < 4; mi++) {
        int oa = o0 + wm * 64 + mi * 16 + gid;
        #pragma unroll
        for (int ni = 0; ni < 4; ni++) {
            int pA = wn * 32 + ni * 8 + 2 * tig;
            #pragma unroll
            for (int r = 0; r < 4; r++) {
                int o = oa + ((r >= 2) ? 8 : 0);
                int p = pA + (r & 1);
                int yy = ty0 + (p >> 4), xx = tx0 + (p & 15);
                size_t gi = (((size_t)(n2 * 512 + o)) << 12) + (yy << 6) + xx;
                out[gi] = acc[mi][ni][r] + g_v[gi];
            }
        }
    }
}

// ----------------------------------------------- K7: final BN stats
__global__ void k_stats(const float* __restrict__ z, const float* __restrict__ gb,
                        const float* __restrict__ bbp) {
    int o = blockIdx.x;
    int tid = threadIdx.x;
    float s = 0.f, sq = 0.f;
    for (int n = 0; n < 2; n++) {
        const float* p = z + ((size_t)(n * 512 + o)) * 4096;
        for (int i = tid; i < 4096; i += 256) { float v = p[i]; s += v; sq += v * v; }
    }
    __shared__ float rs[256], rq[256];
    rs[tid] = s; rq[tid] = sq; __syncthreads();
    for (int st = 128; st > 0; st >>= 1) {
        if (tid < st) { rs[tid] += rs[tid + st]; rq[tid] += rq[tid + st]; }
        __syncthreads();
    }
    if (tid == 0) {
        float mean = rs[0] * (1.f / 8192.f);
        float var = rq[0] * (1.f / 8192.f) - mean * mean;
        float sc = gb[o] * rsqrtf(var + EPS);
        g_scale[o] = sc;
        g_shift[o] = bbp[o] - mean * sc;
    }
}

// ----------------------------------------------- K8: apply BN + lrelu
__global__ void k_apply(float* __restrict__ out) {
    int idx = blockIdx.x * 256 + threadIdx.x;
    if (idx >= 4194304) return;
    int o = (idx >> 12) & 511;
    float v = out[idx] * g_scale[o] + g_shift[o];
    out[idx] = (v >= 0.f) ? v : SLOPE * v;
}

extern "C" void kernel_launch(void* const* d_in, const int* in_sizes, int n_in,
                              void* d_out, int out_size) {
    const float* feats = (const float*)d_in[0];
    const float* w0 = (const float*)d_in[1];
    const float* g0 = (const float*)d_in[2];
    const float* b0 = (const float*)d_in[3];
    const float* w1 = (const float*)d_in[4];
    const float* g1 = (const float*)d_in[5];
    const float* b1 = (const float*)d_in[6];
    const float* w2 = (const float*)d_in[7];
    const float* g2 = (const float*)d_in[8];
    const float* b2 = (const float*)d_in[9];
    const float* w3 = (const float*)d_in[10];
    const float* g3 = (const float*)d_in[11];
    const float* b3 = (const float*)d_in[12];
    const float* wb = (const float*)d_in[13];
    const float* gb = (const float*)d_in[14];
    const float* bb = (const float*)d_in[15];
    float* out = (float*)d_out;

    static bool attr_set = false;
    if (!attr_set) {
        cudaFuncSetAttribute(k_conv3_lg, cudaFuncAttributeMaxDynamicSharedMemorySize, CONV_SMEM);
        attr_set = true;
    }

    k_prepW<<<1024, 512>>>(wb);
    k_prepP<<<dim3(2048, 32), 328>>>(feats);
    k_pool<<<4096, 256>>>(feats);
    k_conv1<<<100, 512>>>(w0, w1, w2, w3);
    k_bnbr<<<2048, 128>>>(g0, b0, g1, b1, g2, b2, g3, b3);
    k_qgemm<<<dim3(9, 8, 4), 128>>>(wb);
    k_upsH<<<(2359296 + 255) / 256, 256>>>();
    k_upsW<<<(4194304 + 255) / 256, 256>>>();
    k_conv3_lg<<<dim3(4, 32), 512, CONV_SMEM>>>(out);
    k_stats<<<512, 256>>>(out, gb, bb);
    k_apply<<<(4194304 + 255) / 256, 256>>>(out);
}

// round 5
// speedup vs baseline: 1.7578x; 1.1083x over previous
#include <cuda_runtime.h>
#include <cuda_fp16.h>
#include <cstdint>

#define EPS   1e-5f
#define SLOPE 0.01f

__constant__ int c_SZ[4] = {1, 2, 3, 6};
__constant__ int c_S2[4] = {1, 4, 9, 36};
__constant__ int c_PO[4] = {0, 1, 5, 14};
__constant__ int c_UB[4] = {0, 196608, 589824, 1179648};

// scratch (static device globals; no allocation)
__device__ float g_pool[204800];
__device__ float g_bo[51200];
__device__ float g_bhat[51200];
__device__ float g_q[460800];
__device__ float g_u[2359296];
__device__ float g_v[4194304];
__device__ float g_scale[512];
__device__ float g_shift[512];
// pre-swizzled FP16 operands for the big conv (stored as 32-bit words = half2)
__device__ uint32_t g_wA[4980736];    // [4 ot][128 chunk][128 o][76 words]   = 19.9MB
__device__ uint32_t g_fB[10747904];   // [32 nb][128 chunk][8 pair][328 words]= 43MB

// ---------------------------------------------------------------- helpers
__device__ __forceinline__ uint32_t smem_u32(const void* p) {
    uint32_t a;
    asm("{ .reg .u64 t; cvta.to.shared.u64 t, %1; cvt.u32.u64 %0, t; }" : "=r"(a) : "l"(p));
    return a;
}
__device__ __forceinline__ void cp16(uint32_t dst, const void* src) {
    asm volatile("cp.async.cg.shared.global [%0], [%1], 16;" :: "r"(dst), "l"(src));
}
__device__ __forceinline__ void cp_commit() {
    asm volatile("cp.async.commit_group;" ::: "memory");
}
template <int N> __device__ __forceinline__ void cp_wait() {
    asm volatile("cp.async.wait_group %0;" :: "n"(N) : "memory");
}
__device__ __forceinline__ void mma16(float* c, uint32_t a0, uint32_t a1, uint32_t a2, uint32_t a3,
                                      uint32_t b0, uint32_t b1) {
    asm volatile("mma.sync.aligned.m16n8k16.row.col.f32.f16.f16.f32 "
                 "{%0,%1,%2,%3}, {%4,%5,%6,%7}, {%8,%9}, {%0,%1,%2,%3};\n"
                 : "+f"(c[0]), "+f"(c[1]), "+f"(c[2]), "+f"(c[3])
                 : "r"(a0), "r"(a1), "r"(a2), "r"(a3), "r"(b0), "r"(b1));
}

// ---------------------------------------------------------------- K1: pools
__global__ void k_pool(const float* __restrict__ feats) {
    __shared__ float plane[4096];
    __shared__ float rowp[768];
    int nc = blockIdx.x;
    const float* src = feats + (size_t)nc * 4096;
    for (int i = threadIdx.x; i < 4096; i += 256) plane[i] = src[i];
    __syncthreads();
    for (int t = threadIdx.x; t < 768; t += 256) {
        int b, loc;
        if (t < 64)       { b = 0; loc = t; }
        else if (t < 192) { b = 1; loc = t - 64; }
        else if (t < 384) { b = 2; loc = t - 192; }
        else              { b = 3; loc = t - 384; }
        int s = c_SZ[b];
        int y = loc / s, j = loc - y * s;
        int xs = (j * 64) / s, xe = ((j + 1) * 64 + s - 1) / s;
        float a = 0.f;
        for (int x = xs; x < xe; x++) a += plane[y * 64 + x];
        rowp[t] = a;
    }
    __syncthreads();
    if (threadIdx.x < 50) {
        int t = threadIdx.x; int b, loc;
        if (t < 1)       { b = 0; loc = 0; }
        else if (t < 5)  { b = 1; loc = t - 1; }
        else if (t < 14) { b = 2; loc = t - 5; }
        else             { b = 3; loc = t - 14; }
        int s = c_SZ[b];
        int i = loc / s, j = loc - i * s;
        int ys = (i * 64) / s, ye = ((i + 1) * 64 + s - 1) / s;
        int xs = (j * 64) / s, xe = ((j + 1) * 64 + s - 1) / s;
        int rb = (b == 0) ? 0 : (b == 1) ? 64 : (b == 2) ? 192 : 384;
        float a = 0.f;
        for (int y = ys; y < ye; y++) a += rowp[rb + y * s + j];
        g_pool[c_PO[b] * 4096 + nc * c_S2[b] + loc] = a / (float)((ye - ys) * (xe - xs));
    }
}

// -------------------------------------- K2: zero accumulator for 1x1 convs
__global__ void k_zero() {
    int i = blockIdx.x * 1024 + threadIdx.x;
    if (i < 51200) g_bo[i] = 0.f;
}

// ----------------------- K2b: 1x1 convs, templated per branch, split-K
template <int S2, int KS>
__global__ void k_conv1t(const float* __restrict__ W, int pofs, int bofs) {
    constexpr int C = 2 * S2;
    constexpr int NA = (C + 3) / 4;
    constexpr int KL = 2048 / KS;
    extern __shared__ float sm[];
    float* Ps = sm;                    // [KL][C]
    float* Ws = sm + KL * C;           // [64][129]
    int o0 = blockIdx.x * 64;
    int k0 = blockIdx.y * KL;
    int tid = threadIdx.x;
    int ol = tid >> 2, l4 = tid & 3;
    float acc[NA];
    #pragma unroll
    for (int a = 0; a < NA; a++) acc[a] = 0.f;

    for (int i = tid; i < KL * C; i += 256) {
        int k = i / C, col = i - k * C;
        int n = col / S2, ij = col - n * S2;
        Ps[i] = g_pool[pofs + n * 2048 * S2 + (k0 + k) * S2 + ij];
    }
    for (int kt = 0; kt < KL; kt += 128) {
        __syncthreads();
        for (int i = tid; i < 8192; i += 256) {
            int o = i >> 7, k = i & 127;
            Ws[o * 129 + k] = W[(size_t)(o0 + o) * 2048 + k0 + kt + k];
        }
        __syncthreads();
        for (int k = 0; k < 128; k++) {
            float w = Ws[ol * 129 + k];
            const float* pr = &Ps[(kt + k) * C];
            #pragma unroll
            for (int a = 0; a < NA; a++) {
                int col = l4 + 4 * a;
                if (col < C) acc[a] += w * pr[col];
            }
        }
    }
    #pragma unroll
    for (int a = 0; a < NA; a++) {
        int col = l4 + 4 * a;
        if (col < C) {
            int n = col / S2, ij = col - n * S2;
            float* dst = &g_bo[bofs + (n * 512 + o0 + ol) * S2 + ij];
            if (KS == 1) *dst = acc[a];
            else atomicAdd(dst, acc[a]);
        }
    }
}

// ---------------------------------------- K3: per-branch BN + lrelu
__global__ void k_bnbr(const float* __restrict__ g0, const float* __restrict__ b0,
                       const float* __restrict__ g1, const float* __restrict__ b1,
                       const float* __restrict__ g2, const float* __restrict__ b2,
                       const float* __restrict__ g3, const float* __restrict__ b3) {
    int b = blockIdx.x >> 9, o = blockIdx.x & 511;
    int s2 = c_S2[b], cnt = 2 * s2;
    int tid = threadIdx.x;
    __shared__ float rs[128], rq[128];
    float v = 0.f; int idx = 0;
    if (tid < cnt) {
        int n = tid / s2, ij = tid - n * s2;
        idx = c_PO[b] * 1024 + (n * 512 + o) * s2 + ij;
        v = g_bo[idx];
    }
    rs[tid] = (tid < cnt) ? v : 0.f;
    rq[tid] = (tid < cnt) ? v * v : 0.f;
    __syncthreads();
    for (int st = 64; st > 0; st >>= 1) {
        if (tid < st) { rs[tid] += rs[tid + st]; rq[tid] += rq[tid + st]; }
        __syncthreads();
    }
    float mean = rs[0] / cnt, var = rq[0] / cnt - mean * mean;
    const float* gp = (b == 0) ? g0 : (b == 1) ? g1 : (b == 2) ? g2 : g3;
    const float* bp = (b == 0) ? b0 : (b == 1) ? b1 : (b == 2) ? b2 : b3;
    float sc = gp[o] * rsqrtf(var + EPS);
    float sh = bp[o] - mean * sc;
    if (tid < cnt) {
        float y = v * sc + sh;
        g_bhat[idx] = (y >= 0.f) ? y : SLOPE * y;
    }
}

// ---------------- K4: q-GEMM (branch channels 0..2047 of wb)
__global__ void k_qgemm(const float* __restrict__ wb) {
    int tap = blockIdx.x, ot = blockIdx.y, b = blockIdx.z;
    int s2 = c_S2[b];
    __shared__ float sm[64][72];
    int ol = threadIdx.x & 63, n = threadIdx.x >> 6;
    int o = ot * 64 + ol;
    float acc[36];
    #pragma unroll
    for (int e = 0; e < 36; e++) acc[e] = 0.f;
    int basec = 512 * b;
    for (int cc = 0; cc < 512; cc += 64) {
        __syncthreads();
        int tot = 64 * 2 * s2;
        for (int t = threadIdx.x; t < tot; t += 128) {
            int c = t / (2 * s2), r = t - c * (2 * s2);
            int nn = r / s2, ij = r - nn * s2;
            sm[c][r] = g_bhat[c_PO[b] * 1024 + (nn * 512 + cc + c) * s2 + ij];
        }
        __syncthreads();
        for (int c = 0; c < 64; c++) {
            float wv = wb[(size_t)(o * 4096 + basec + cc + c) * 9 + tap];
            const float* row = &sm[c][n * s2];
            #pragma unroll
            for (int e = 0; e < 36; e++)
                if (e < s2) acc[e] += wv * row[e];
        }
    }
    int qb = c_PO[b] * 9216;
    for (int e = 0; e < s2; e++)
        g_q[qb + ((n * 512 + o) * 9 + tap) * s2 + e] = acc[e];
}

// ------------- K5a: H upsample
__global__ void k_upsH() {
    int idx = blockIdx.x * 256 + threadIdx.x;
    if (idx >= 2359296) return;
    int b, loc;
    if (idx < 196608)       { b = 0; loc = idx; }
    else if (idx < 589824)  { b = 1; loc = idx - 196608; }
    else if (idx < 1179648) { b = 2; loc = idx - 589824; }
    else                    { b = 3; loc = idx - 1179648; }
    int s = c_SZ[b], s2 = c_S2[b];
    int j = loc % s; int t = loc / s;
    int y = t & 63; t >>= 6;
    int kx = t % 3; t /= 3;
    int o = t & 511; int n = t >> 9;
    int qb = c_PO[b] * 9216;
    float fs = (s > 1) ? (float)(s - 1) / 63.0f : 0.0f;
    float acc = 0.f;
    #pragma unroll
    for (int ky = 0; ky < 3; ky++) {
        int Y = y + ky - 1;
        if (Y < 0 || Y > 63) continue;
        float pos = Y * fs;
        int i0 = (int)pos; float w = pos - i0; int i1 = min(i0 + 1, s - 1);
        const float* qq = &g_q[qb + ((n * 512 + o) * 9 + ky * 3 + kx) * s2 + j];
        acc += (1.f - w) * qq[i0 * s] + w * qq[i1 * s];
    }
    g_u[c_UB[b] + loc] = acc;
}

// ------------- K5b: W upsample + branch sum -> v
__global__ void k_upsW() {
    int idx = blockIdx.x * 256 + threadIdx.x;
    if (idx >= 4194304) return;
    int x = idx & 63, y = (idx >> 6) & 63;
    int no = idx >> 12;
    float acc = 0.f;
    #pragma unroll
    for (int b = 0; b < 4; b++) {
        int s = c_SZ[b];
        float fs = (s > 1) ? (float)(s - 1) / 63.f : 0.f;
        #pragma unroll
        for (int kx = 0; kx < 3; kx++) {
            int X = x + kx - 1;
            if (X < 0 || X > 63) continue;
            float pos = X * fs;
            int j0 = (int)pos; float w = pos - j0; int j1 = min(j0 + 1, s - 1);
            const float* uu = &g_u[c_UB[b] + ((no * 3 + kx) * 64 + y) * s];
            acc += (1.f - w) * uu[j0] + w * uu[j1];
        }
    }
    g_v[idx] = acc;
}

// ----------------- prep: weights -> fp16 half2 words [ot][chunk][o 128][76]
// word w = tap*8 + p (p = channel-pair); channels c = 16*chunk + 2p, 2p+1.
__global__ void k_prepW(const float* __restrict__ wb) {
    int ot = blockIdx.x >> 7, j = blockIdx.x & 127;
    size_t dbase = (size_t)blockIdx.x * 9728;
    for (int w = threadIdx.x; w < 9728; w += 512) {
        int o = w / 76, r = w - o * 76;
        uint32_t val = 0u;
        if (r < 72) {
            int tap = r >> 3, p = r & 7;
            int c = j * 16 + 2 * p;
            const float* src = wb + ((size_t)(ot * 128 + o) * 4096 + 2048 + c) * 9 + tap;
            __half2 h = __floats2half2_rn(src[0], src[9]);
            val = *reinterpret_cast<uint32_t*>(&h);
        }
        g_wA[dbase + w] = val;
    }
}

// ----------------- prep: patches -> fp16 half2 words [nb][chunk][pair 8][328]
__global__ void k_prepP(const float* __restrict__ feats) {
    int j = blockIdx.x;           // chunk 0..127
    int nb = blockIdx.y;          // 0..31
    int n = nb >> 4, t = nb & 15;
    int ty0 = (t >> 2) * 16, tx0 = (t & 3) * 16;
    size_t dbase = (size_t)(nb * 128 + j) * 2624;
    for (int i = threadIdx.x; i < 2592; i += 512) {
        int p = i / 324, rr = i - p * 324;
        int y = rr / 18, x = rr - y * 18;
        int gy = ty0 + y - 1, gx = tx0 + x - 1;
        uint32_t val = 0u;
        if ((unsigned)gy < 64u && (unsigned)gx < 64u) {
            int c = j * 16 + 2 * p;
            const float* s = feats + (((size_t)(n * 2048 + c)) << 12) + (gy << 6) + gx;
            __half2 h = __floats2half2_rn(s[0], s[4096]);
            val = *reinterpret_cast<uint32_t*>(&h);
        }
        g_fB[dbase + p * 328 + rr] = val;
    }
}

// ======================= K6: conv3x3 via FP16 mma.m16n8k16 =================
// CTA: 128 o x 256 px. 16 warps (wm2 x wn8). Chunk = 16 channels, 128 chunks.
// K-order per chunk: 9 taps x 16 channels (one k16 mma per tap per tile).
#define ABYTES  38912u       // 128*76*4
#define PBYTES  10496u       // 8*328*4
#define STAGEB  49408u
#define NCP     3088
#define NCPA    2432
#define CONV_SMEM (3 * STAGEB)   // 148224

__global__ __launch_bounds__(512, 1) void k_conv3_h(float* __restrict__ out) {
    extern __shared__ char smem[];
    uint32_t sb = smem_u32(smem);
    int tid = threadIdx.x;
    int warp = tid >> 5, lane = tid & 31;
    int bx = blockIdx.x;          // o-tile 0..3
    int nb = blockIdx.y;          // 0..31
    int o0 = bx * 128;
    int n2 = nb >> 4;
    int t = nb & 15;
    int ty0 = (t >> 2) * 16, tx0 = (t & 3) * 16;
    int wm = warp >> 3, wn = warp & 7;
    int gid = lane >> 2, tig = lane & 3;

    float acc[4][4][4];
    #pragma unroll
    for (int mi = 0; mi < 4; mi++)
        #pragma unroll
        for (int ni = 0; ni < 4; ni++)
            #pragma unroll
            for (int r = 0; r < 4; r++) acc[mi][ni][r] = 0.f;

    int py[4], px[4];
    #pragma unroll
    for (int ni = 0; ni < 4; ni++) {
        int p = wn * 32 + ni * 8 + gid;
        py[ni] = p >> 4; px[ni] = p & 15;
    }

    const char* srcAbase = (const char*)(g_wA + (size_t)bx * 128 * 9728);
    const char* srcPbase = (const char*)(g_fB + (size_t)nb * 128 * 2624);

    auto stage = [&](int j) {
        uint32_t dA = sb + (j % 3) * STAGEB;
        uint32_t dP = dA + ABYTES;
        const char* sA = srcAbase + (size_t)j * ABYTES;
        const char* sP = srcPbase + (size_t)j * PBYTES;
        for (int i = tid; i < NCP; i += 512) {
            if (i < NCPA) cp16(dA + i * 16, sA + i * 16);
            else          cp16(dP + (i - NCPA) * 16, sP + (size_t)(i - NCPA) * 16);
        }
        cp_commit();
    };

    stage(0);
    stage(1);

    for (int j = 0; j < 128; j++) {
        if (j < 127) cp_wait<1>(); else cp_wait<0>();
        __syncthreads();
        if (j + 2 < 128) stage(j + 2);

        const uint32_t* As = (const uint32_t*)(smem + (j % 3) * STAGEB);
        const uint32_t* Ps = As + 9728;

        #pragma unroll
        for (int ky = 0; ky < 3; ky++) {
            #pragma unroll
            for (int kx = 0; kx < 3; kx++) {
                int tap8 = (ky * 3 + kx) * 8;
                uint32_t bf[4][2];
                #pragma unroll
                for (int ni = 0; ni < 4; ni++) {
                    int off = (py[ni] + ky) * 18 + px[ni] + kx;
                    bf[ni][0] = Ps[tig * 328 + off];
                    bf[ni][1] = Ps[(tig + 4) * 328 + off];
                }
                #pragma unroll
                for (int mi = 0; mi < 4; mi++) {
                    int m = wm * 64 + mi * 16 + gid;
                    uint32_t a0 = As[m * 76 + tap8 + tig];
                    uint32_t a1 = As[(m + 8) * 76 + tap8 + tig];
                    uint32_t a2 = As[m * 76 + tap8 + tig + 4];
                    uint32_t a3 = As[(m + 8) * 76 + tap8 + tig + 4];
                    #pragma unroll
                    for (int ni = 0; ni < 4; ni++)
                        mma16(acc[mi][ni], a0, a1, a2, a3, bf[ni][0], bf[ni][1]);
                }
            }
        }
        __syncthreads();
    }

    // epilogue: z = conv(feats) + branch contribution v; store pre-BN z
    #pragma unroll
    for (int mi = 0; mi < 4; mi++) {
        int oa = o0 + wm * 64 + mi * 16 + gid;
        #pragma unroll
        for (int ni = 0; ni < 4; ni++) {
            int pA = wn * 32 + ni * 8 + 2 * tig;
            #pragma unroll
            for (int r = 0; r < 4; r++) {
                int o = oa + ((r >= 2) ? 8 : 0);
                int p = pA + (r & 1);
                int yy = ty0 + (p >> 4), xx = tx0 + (p & 15);
                size_t gi = (((size_t)(n2 * 512 + o)) << 12) + (yy << 6) + xx;
                out[gi] = acc[mi][ni][r] + g_v[gi];
            }
        }
    }
}

// ----------------------------------------------- K7: final BN stats
__global__ void k_stats(const float* __restrict__ z, const float* __restrict__ gb,
                        const float* __restrict__ bbp) {
    int o = blockIdx.x;
    int tid = threadIdx.x;
    float s = 0.f, sq = 0.f;
    for (int n = 0; n < 2; n++) {
        const float* p = z + ((size_t)(n * 512 + o)) * 4096;
        for (int i = tid; i < 4096; i += 256) { float v = p[i]; s += v; sq += v * v; }
    }
    __shared__ float rs[256], rq[256];
    rs[tid] = s; rq[tid] = sq; __syncthreads();
    for (int st = 128; st > 0; st >>= 1) {
        if (tid < st) { rs[tid] += rs[tid + st]; rq[tid] += rq[tid + st]; }
        __syncthreads();
    }
    if (tid == 0) {
        float mean = rs[0] * (1.f / 8192.f);
        float var = rq[0] * (1.f / 8192.f) - mean * mean;
        float sc = gb[o] * rsqrtf(var + EPS);
        g_scale[o] = sc;
        g_shift[o] = bbp[o] - mean * sc;
    }
}

// ----------------------------------------------- K8: apply BN + lrelu
__global__ void k_apply(float* __restrict__ out) {
    int idx = blockIdx.x * 256 + threadIdx.x;
    if (idx >= 4194304) return;
    int o = (idx >> 12) & 511;
    float v = out[idx] * g_scale[o] + g_shift[o];
    out[idx] = (v >= 0.f) ? v : SLOPE * v;
}

extern "C" void kernel_launch(void* const* d_in, const int* in_sizes, int n_in,
                              void* d_out, int out_size) {
    const float* feats = (const float*)d_in[0];
    const float* w0 = (const float*)d_in[1];
    const float* g0 = (const float*)d_in[2];
    const float* b0 = (const float*)d_in[3];
    const float* w1 = (const float*)d_in[4];
    const float* g1 = (const float*)d_in[5];
    const float* b1 = (const float*)d_in[6];
    const float* w2 = (const float*)d_in[7];
    const float* g2 = (const float*)d_in[8];
    const float* b2 = (const float*)d_in[9];
    const float* w3 = (const float*)d_in[10];
    const float* g3 = (const float*)d_in[11];
    const float* b3 = (const float*)d_in[12];
    const float* wb = (const float*)d_in[13];
    const float* gb = (const float*)d_in[14];
    const float* bb = (const float*)d_in[15];
    float* out = (float*)d_out;

    static bool attr_set = false;
    if (!attr_set) {
        cudaFuncSetAttribute(k_conv3_h, cudaFuncAttributeMaxDynamicSharedMemorySize, CONV_SMEM);
        cudaFuncSetAttribute(k_conv1t<1, 1>, cudaFuncAttributeMaxDynamicSharedMemorySize, 110000);
        cudaFuncSetAttribute(k_conv1t<4, 1>, cudaFuncAttributeMaxDynamicSharedMemorySize, 110000);
        cudaFuncSetAttribute(k_conv1t<9, 2>, cudaFuncAttributeMaxDynamicSharedMemorySize, 110000);
        cudaFuncSetAttribute(k_conv1t<36, 8>, cudaFuncAttributeMaxDynamicSharedMemorySize, 110000);
        attr_set = true;
    }

    k_prepW<<<512, 512>>>(wb);
    k_prepP<<<dim3(128, 32), 512>>>(feats);
    k_pool<<<4096, 256>>>(feats);
    k_zero<<<50, 1024>>>();
    k_conv1t<1, 1><<<dim3(8, 1), 256, (2048 * 2 + 64 * 129) * 4>>>(w0, 0 * 4096, 0 * 1024);
    k_conv1t<4, 1><<<dim3(8, 1), 256, (2048 * 8 + 64 * 129) * 4>>>(w1, 1 * 4096, 1 * 1024);
    k_conv1t<9, 2><<<dim3(8, 2), 256, (1024 * 18 + 64 * 129) * 4>>>(w2, 5 * 4096, 5 * 1024);
    k_conv1t<36, 8><<<dim3(8, 8), 256, (256 * 72 + 64 * 129) * 4>>>(w3, 14 * 4096, 14 * 1024);
    k_bnbr<<<2048, 128>>>(g0, b0, g1, b1, g2, b2, g3, b3);
    k_qgemm<<<dim3(9, 8, 4), 128>>>(wb);
    k_upsH<<<(2359296 + 255) / 256, 256>>>();
    k_upsW<<<(4194304 + 255) / 256, 256>>>();
    k_conv3_h<<<dim3(4, 32), 512, CONV_SMEM>>>(out);
    k_stats<<<512, 256>>>(out, gb, bb);
    k_apply<<<(4194304 + 255) / 256, 256>>>(out);
}